// round 2
// baseline (speedup 1.0000x reference)
#include <cuda_runtime.h>
#include <math_constants.h>

// Problem constants (fixed by the reference)
#define BB 2
#define TT 512
#define EE 1024
#define SS 2048
#define AA 30

// Scratch for precomputed head scores: relu(x @ W + b), shape (B*T)
__device__ float g_scores[BB * TT];

// ---------------------------------------------------------------------------
// Kernel 1: scores[b,t] = relu(dot(x[b,t,:], W) + bias)
// One warp per row. 1024 floats per row -> 8 float4 per lane.
// ---------------------------------------------------------------------------
__global__ void score_kernel(const float* __restrict__ x,
                             const float* __restrict__ W,
                             const float* __restrict__ bias) {
    const int row  = blockIdx.x * 8 + (threadIdx.x >> 5);   // B*T = 1024 rows
    const int lane = threadIdx.x & 31;

    const float4* __restrict__ xr = reinterpret_cast<const float4*>(x + (size_t)row * EE);
    const float4* __restrict__ w4 = reinterpret_cast<const float4*>(W);

    float acc = 0.0f;
#pragma unroll
    for (int i = 0; i < 8; ++i) {
        const float4 xv = xr[lane + i * 32];
        const float4 wv = w4[lane + i * 32];
        acc += xv.x * wv.x + xv.y * wv.y + xv.z * wv.z + xv.w * wv.w;
    }
#pragma unroll
    for (int off = 16; off; off >>= 1)
        acc += __shfl_xor_sync(0xffffffffu, acc, off);

    if (lane == 0)
        g_scores[row] = fmaxf(acc + bias[0], 0.0f);
}

// ---------------------------------------------------------------------------
// Kernel 2: one WARP per (span, batch). No shared memory, no __syncthreads.
//   - softmax of <=30 scores held in registers, broadcast via shfl
//   - each lane owns 8 float4 columns (32 lanes * 8 * 4 = 1024 = E)
//   - per j-step: 8 independent LDG.128 -> high MLP, L2 latency hidden
// ---------------------------------------------------------------------------
__global__ __launch_bounds__(256)
void span_kernel(const float* __restrict__ x,
                 const int* __restrict__ start,
                 const int* __restrict__ end,
                 float* __restrict__ out) {
    const int wid  = blockIdx.x * 8 + (threadIdx.x >> 5);  // 0 .. 4095
    const int lane = threadIdx.x & 31;

    const int s = wid & (SS - 1);
    const int b = wid >> 11;            // SS = 2048 = 2^11

    const int t0 = start[s];
    const int w  = end[s] - t0 + 1;     // 1..30; t0 + w - 1 <= T-1 guaranteed

    // ---- warp softmax over the w valid scores (lane j holds p_j) ----
    float sc = (lane < w) ? g_scores[b * TT + t0 + lane] : -CUDART_INF_F;
    float m = sc;
#pragma unroll
    for (int off = 16; off; off >>= 1)
        m = fmaxf(m, __shfl_xor_sync(0xffffffffu, m, off));
    float e = (lane < w) ? __expf(sc - m) : 0.0f;
    float sum = e;
#pragma unroll
    for (int off = 16; off; off >>= 1)
        sum += __shfl_xor_sync(0xffffffffu, sum, off);
    const float p = e / sum;            // p = 0 for lane >= w

    // ---- weighted sum of gathered rows ----
    const float4* __restrict__ xb =
        reinterpret_cast<const float4*>(x + ((size_t)b * TT + t0) * EE);

    float4 acc[8];
#pragma unroll
    for (int k = 0; k < 8; ++k)
        acc[k] = make_float4(0.0f, 0.0f, 0.0f, 0.0f);

    for (int j = 0; j < w; ++j) {
        const float pj = __shfl_sync(0xffffffffu, p, j);
        const float4* __restrict__ row = xb + (size_t)j * (EE / 4);
        float4 v[8];
#pragma unroll
        for (int k = 0; k < 8; ++k)
            v[k] = row[lane + 32 * k];   // 8 independent 16B loads in flight
#pragma unroll
        for (int k = 0; k < 8; ++k) {
            acc[k].x += pj * v[k].x;
            acc[k].y += pj * v[k].y;
            acc[k].z += pj * v[k].z;
            acc[k].w += pj * v[k].w;
        }
    }

    float4* __restrict__ o =
        reinterpret_cast<float4*>(out + ((size_t)b * SS + s) * EE);
#pragma unroll
    for (int k = 0; k < 8; ++k)
        o[lane + 32 * k] = acc[k];
}

// ---------------------------------------------------------------------------
// Launch
// Inputs (metadata order): x (B,T,E) f32, W (E,1) f32, b (1,) f32,
//                          start (S,) i32, end (S,) i32
// Output: (B, S, E) f32
// ---------------------------------------------------------------------------
extern "C" void kernel_launch(void* const* d_in, const int* in_sizes, int n_in,
                              void* d_out, int out_size) {
    const float* x     = (const float*)d_in[0];
    const float* W     = (const float*)d_in[1];
    const float* bias  = (const float*)d_in[2];
    const int*   start = (const int*)d_in[3];
    const int*   end   = (const int*)d_in[4];
    float*       out   = (float*)d_out;

    // Kernel 1: B*T = 1024 rows, 8 warps/block -> 128 blocks
    score_kernel<<<(BB * TT) / 8, 256>>>(x, W, bias);

    // Kernel 2: one warp per (span, batch): 4096 warps -> 512 blocks x 256 thr
    span_kernel<<<(BB * SS * 32) / 256, 256>>>(x, start, end, out);
}